// round 4
// baseline (speedup 1.0000x reference)
#include <cuda_runtime.h>
#include <math.h>

namespace {
constexpr int SEQ   = 1024;
constexpr int EMBD  = 512;
constexpr int NHEAD = 8;
constexpr int HDIM  = 64;
constexpr int BATCH = 2;
constexpr int ROWS  = BATCH * SEQ;   // 2048
constexpr int QSTR  = 68;            // padded smem stride for 64-wide tiles
}

// ---------------- device scratch (36 MB) ----------------
__device__ __align__(16) float g_qc_u[ROWS * EMBD];
__device__ __align__(16) float g_qp_u[ROWS * EMBD];
__device__ __align__(16) float g_qc_f[ROWS * EMBD];
__device__ __align__(16) float g_qp_f[ROWS * EMBD];
__device__ __align__(16) float g_kh [ROWS * EMBD];
__device__ __align__(16) float g_vh [ROWS * EMBD];
__device__ __align__(16) float g_kph[ROWS * EMBD];
__device__ __align__(16) float g_attn_u[ROWS * EMBD];
__device__ __align__(16) float g_attn_f[ROWS * EMBD];

__device__ __forceinline__ float tanh_fast(float x) {
    x = fminf(fmaxf(x, -20.f), 20.f);
    float e = __expf(2.f * x);
    return __fdividef(e - 1.f, e + 1.f);
}

// ================= projection GEMMs (fused bias + tanh epilogues) ==========
// z=0: qu = f_emb@Wu_w+Wu_b  -> qc_u=tanh(qu+Buc), qp_u=tanh(qu+Bup)
// z=1: qf = f_emb@Wq_w+Wq_b  -> qc_f=tanh(qf+Bfc), qp_f=tanh(qf+Bfp)
// z=2: kv = f_emb@Wkv_w+b    -> kh=tanh(k), vh=tanh(v)
// z=3: kp = gpe@Wp_w+Wp_b    -> kph=tanh(kp)
__global__ __launch_bounds__(256)
void proj_kernel(const float* __restrict__ f_emb, const float* __restrict__ gpe,
                 const float* __restrict__ Wu_w, const float* __restrict__ Wu_b,
                 const float* __restrict__ Wq_w, const float* __restrict__ Wq_b,
                 const float* __restrict__ Wkv_w, const float* __restrict__ Wkv_b,
                 const float* __restrict__ Wp_w, const float* __restrict__ Wp_b,
                 const float* __restrict__ Buc, const float* __restrict__ Bup,
                 const float* __restrict__ Bfc, const float* __restrict__ Bfp)
{
    const int z = blockIdx.z;
    const float* A; const float* W; const float* bias; int K, N;
    if (z == 0)      { A = f_emb; W = Wu_w;  bias = Wu_b;  K = 512; N = 512;  }
    else if (z == 1) { A = f_emb; W = Wq_w;  bias = Wq_b;  K = 512; N = 512;  }
    else if (z == 2) { A = f_emb; W = Wkv_w; bias = Wkv_b; K = 512; N = 1024; }
    else             { A = gpe;   W = Wp_w;  bias = Wp_b;  K = 128; N = 512;  }

    const int n0 = blockIdx.x * 64;
    if (n0 >= N) return;
    const int m0 = blockIdx.y * 64;

    __shared__ float As[64][20];
    __shared__ float Bs[16][QSTR];

    const int tid = threadIdx.x;
    const int tx  = tid & 15, ty = tid >> 4;

    float acc[4][4];
#pragma unroll
    for (int i = 0; i < 4; i++)
#pragma unroll
        for (int j = 0; j < 4; j++) acc[i][j] = 0.f;

    const int arow = tid >> 2;       // 0..63
    const int adq  = (tid & 3) * 4;  // 0,4,8,12
    const int brow = tid >> 4;       // 0..15
    const int bdq  = (tid & 15) * 4; // 0..60

    for (int kb = 0; kb < K; kb += 16) {
        float4 av = *(const float4*)&A[(m0 + arow) * K + kb + adq];
        float4 bv = *(const float4*)&W[(kb + brow) * N + n0 + bdq];
        __syncthreads();
        *(float4*)&As[arow][adq] = av;
        *(float4*)&Bs[brow][bdq] = bv;
        __syncthreads();
#pragma unroll
        for (int k = 0; k < 16; k++) {
            float a0 = As[ty*4+0][k], a1 = As[ty*4+1][k];
            float a2 = As[ty*4+2][k], a3 = As[ty*4+3][k];
            float4 b4 = *(const float4*)&Bs[k][tx*4];
            acc[0][0] += a0*b4.x; acc[0][1] += a0*b4.y; acc[0][2] += a0*b4.z; acc[0][3] += a0*b4.w;
            acc[1][0] += a1*b4.x; acc[1][1] += a1*b4.y; acc[1][2] += a1*b4.z; acc[1][3] += a1*b4.w;
            acc[2][0] += a2*b4.x; acc[2][1] += a2*b4.y; acc[2][2] += a2*b4.z; acc[2][3] += a2*b4.w;
            acc[3][0] += a3*b4.x; acc[3][1] += a3*b4.y; acc[3][2] += a3*b4.z; acc[3][3] += a3*b4.w;
        }
    }

#pragma unroll
    for (int i = 0; i < 4; i++) {
        int row = m0 + ty*4 + i;
#pragma unroll
        for (int jj = 0; jj < 4; jj++) {
            int col = n0 + tx*4 + jj;
            float v = acc[i][jj] + bias[col];
            if (z == 0) {
                g_qc_u[row*EMBD + col] = tanh_fast(v + Buc[col]);
                g_qp_u[row*EMBD + col] = tanh_fast(v + Bup[col]);
            } else if (z == 1) {
                g_qc_f[row*EMBD + col] = tanh_fast(v + Bfc[col]);
                g_qp_f[row*EMBD + col] = tanh_fast(v + Bfp[col]);
            } else if (z == 2) {
                if (col < EMBD) g_kh[row*EMBD + col]        = tanh_fast(v);
                else            g_vh[row*EMBD + col - EMBD] = tanh_fast(v);
            } else {
                g_kph[row*EMBD + col] = tanh_fast(v);
            }
        }
    }
}

// ================= causal flash attention (two score components) ===========
// Score(j,k) = (qc_j . kh_k + qp_{j'} . kph_k) / 8, with j' = j+1 for batch 0
// (zero row at j=1023), j' = j for batch 1 (faithful _rel_shift semantics).
__global__ __launch_bounds__(256, 2)
void attn_kernel()
{
    extern __shared__ float sm[];
    float* sQc = sm;
    float* sQp = sQc + 64*QSTR;
    float* sK  = sQp + 64*QSTR;
    float* sKp = sK  + 64*QSTR;
    float* sV  = sKp + 64*QSTR;
    float* sP  = sV  + 64*QSTR;

    const int jt = 15 - (int)blockIdx.x;   // long blocks first
    const int bn = blockIdx.y;
    const int b  = bn >> 3;
    const int n  = bn & 7;
    const int st = blockIdx.z;

    const float* __restrict__ qc = st ? g_qc_f : g_qc_u;
    const float* __restrict__ qp = st ? g_qp_f : g_qp_u;
    float* __restrict__ outp     = st ? g_attn_f : g_attn_u;

    const int tid = threadIdx.x;
    const int tx  = tid & 15, ty = tid >> 4;

    // ---- load Q tiles (qc straight; qp with rel_shift row offset) ----
    const int qoff = (b == 0) ? 1 : 0;
#pragma unroll
    for (int it = 0; it < 4; it++) {
        int f  = tid + 256*it;
        int r  = f >> 4;
        int dq = (f & 15) * 4;
        int jg = jt*64 + r;
        int grow = (b*SEQ + jg) * EMBD + n*HDIM + dq;
        *(float4*)&sQc[r*QSTR + dq] = *(const float4*)&qc[grow];
        float4 pv;
        if (b == 0 && jg == SEQ - 1) pv = make_float4(0.f, 0.f, 0.f, 0.f);
        else                         pv = *(const float4*)&qp[grow + qoff*EMBD];
        *(float4*)&sQp[r*QSTR + dq] = pv;
    }

    float m[4], l[4], O[4][4];
#pragma unroll
    for (int i = 0; i < 4; i++) {
        m[i] = -1e30f; l[i] = 0.f;
#pragma unroll
        for (int c = 0; c < 4; c++) O[i][c] = 0.f;
    }

    for (int kt = 0; kt <= jt; kt++) {
        __syncthreads();   // previous PV / Q writes drained
#pragma unroll
        for (int it = 0; it < 4; it++) {
            int f  = tid + 256*it;
            int r  = f >> 4;
            int dq = (f & 15) * 4;
            int grow = (b*SEQ + kt*64 + r) * EMBD + n*HDIM + dq;
            *(float4*)&sK [r*QSTR + dq] = *(const float4*)&g_kh [grow];
            *(float4*)&sKp[r*QSTR + dq] = *(const float4*)&g_kph[grow];
            *(float4*)&sV [r*QSTR + dq] = *(const float4*)&g_vh [grow];
        }
        __syncthreads();

        // ---- scores: rows ty*4+i, cols tx+16*jj ----
        float s[4][4];
#pragma unroll
        for (int i = 0; i < 4; i++)
#pragma unroll
            for (int j = 0; j < 4; j++) s[i][j] = 0.f;

#pragma unroll 2
        for (int d = 0; d < 64; d += 4) {
            float4 q0 = *(const float4*)&sQc[(ty*4+0)*QSTR + d];
            float4 q1 = *(const float4*)&sQc[(ty*4+1)*QSTR + d];
            float4 q2 = *(const float4*)&sQc[(ty*4+2)*QSTR + d];
            float4 q3 = *(const float4*)&sQc[(ty*4+3)*QSTR + d];
            float4 p0 = *(const float4*)&sQp[(ty*4+0)*QSTR + d];
            float4 p1 = *(const float4*)&sQp[(ty*4+1)*QSTR + d];
            float4 p2 = *(const float4*)&sQp[(ty*4+2)*QSTR + d];
            float4 p3 = *(const float4*)&sQp[(ty*4+3)*QSTR + d];
#pragma unroll
            for (int jj = 0; jj < 4; jj++) {
                int c = tx + 16*jj;
                float4 k4 = *(const float4*)&sK [c*QSTR + d];
                float4 c4 = *(const float4*)&sKp[c*QSTR + d];
                s[0][jj] += q0.x*k4.x + q0.y*k4.y + q0.z*k4.z + q0.w*k4.w
                          + p0.x*c4.x + p0.y*c4.y + p0.z*c4.z + p0.w*c4.w;
                s[1][jj] += q1.x*k4.x + q1.y*k4.y + q1.z*k4.z + q1.w*k4.w
                          + p1.x*c4.x + p1.y*c4.y + p1.z*c4.z + p1.w*c4.w;
                s[2][jj] += q2.x*k4.x + q2.y*k4.y + q2.z*k4.z + q2.w*k4.w
                          + p2.x*c4.x + p2.y*c4.y + p2.z*c4.z + p2.w*c4.w;
                s[3][jj] += q3.x*k4.x + q3.y*k4.y + q3.z*k4.z + q3.w*k4.w
                          + p3.x*c4.x + p3.y*c4.y + p3.z*c4.z + p3.w*c4.w;
            }
        }

        // ---- online softmax ----
        const bool diag = (kt == jt);
#pragma unroll
        for (int i = 0; i < 4; i++) {
            int rloc = ty*4 + i;
            float sv[4];
            float mt = -1e30f;
#pragma unroll
            for (int jj = 0; jj < 4; jj++) {
                float v = s[i][jj] * 0.125f;   // 1/sqrt(64)
                if (diag && (tx + 16*jj) > rloc) v = -1e30f;
                sv[jj] = v;
                mt = fmaxf(mt, v);
            }
#pragma unroll
            for (int off = 8; off > 0; off >>= 1)
                mt = fmaxf(mt, __shfl_xor_sync(0xffffffffu, mt, off));
            float mnew  = fmaxf(m[i], mt);
            float scale = __expf(m[i] - mnew);
            float lsum  = 0.f;
#pragma unroll
            for (int jj = 0; jj < 4; jj++) {
                float p = __expf(sv[jj] - mnew);
                sP[rloc*QSTR + tx + 16*jj] = p;
                lsum += p;
            }
#pragma unroll
            for (int off = 8; off > 0; off >>= 1)
                lsum += __shfl_xor_sync(0xffffffffu, lsum, off);
            l[i] = l[i]*scale + lsum;
            m[i] = mnew;
#pragma unroll
            for (int c = 0; c < 4; c++) O[i][c] *= scale;
        }
        __syncthreads();

        // ---- PV: O rows ty*4+i, d-cols tx*4..+3 ----
#pragma unroll 4
        for (int kk = 0; kk < 64; kk++) {
            float4 v4 = *(const float4*)&sV[kk*QSTR + tx*4];
            float p0 = sP[(ty*4+0)*QSTR + kk];
            float p1 = sP[(ty*4+1)*QSTR + kk];
            float p2 = sP[(ty*4+2)*QSTR + kk];
            float p3 = sP[(ty*4+3)*QSTR + kk];
            O[0][0] += p0*v4.x; O[0][1] += p0*v4.y; O[0][2] += p0*v4.z; O[0][3] += p0*v4.w;
            O[1][0] += p1*v4.x; O[1][1] += p1*v4.y; O[1][2] += p1*v4.z; O[1][3] += p1*v4.w;
            O[2][0] += p2*v4.x; O[2][1] += p2*v4.y; O[2][2] += p2*v4.z; O[2][3] += p2*v4.w;
            O[3][0] += p3*v4.x; O[3][1] += p3*v4.y; O[3][2] += p3*v4.z; O[3][3] += p3*v4.w;
        }
    }

#pragma unroll
    for (int i = 0; i < 4; i++) {
        float inv = __fdividef(1.f, l[i]);
        int jg = jt*64 + ty*4 + i;
        float4 o = make_float4(O[i][0]*inv, O[i][1]*inv, O[i][2]*inv, O[i][3]*inv);
        *(float4*)&outp[(b*SEQ + jg)*EMBD + n*HDIM + tx*4] = o;
    }
}

// ================= residual + LayerNorm (eps 1e-5, no affine) ==============
__global__ __launch_bounds__(256)
void ln_kernel(const float* __restrict__ u_emb, const float* __restrict__ f_emb,
               float* __restrict__ out)
{
    const int row = blockIdx.x;           // 0..2047
    const int st  = blockIdx.y;           // 0=u, 1=f
    const float* emb  = st ? f_emb   : u_emb;
    const float* attn = st ? g_attn_f : g_attn_u;
    const int t = threadIdx.x;

    float x0 = emb[row*EMBD + t]       + attn[row*EMBD + t];
    float x1 = emb[row*EMBD + t + 256] + attn[row*EMBD + t + 256];

    __shared__ float red[16];
    float s = x0 + x1;
#pragma unroll
    for (int off = 16; off > 0; off >>= 1) s += __shfl_xor_sync(0xffffffffu, s, off);
    if ((t & 31) == 0) red[t >> 5] = s;
    __syncthreads();
    float tot = red[0]+red[1]+red[2]+red[3]+red[4]+red[5]+red[6]+red[7];
    float mean = tot * (1.f / 512.f);

    float d0 = x0 - mean, d1 = x1 - mean;
    float q = d0*d0 + d1*d1;
#pragma unroll
    for (int off = 16; off > 0; off >>= 1) q += __shfl_xor_sync(0xffffffffu, q, off);
    if ((t & 31) == 0) red[8 + (t >> 5)] = q;
    __syncthreads();
    float vtot = red[8]+red[9]+red[10]+red[11]+red[12]+red[13]+red[14]+red[15];
    float inv = rsqrtf(vtot * (1.f / 512.f) + 1e-5f);

    size_t base = (size_t)st * ROWS * EMBD + (size_t)row * EMBD;
    out[base + t]       = d0 * inv;
    out[base + t + 256] = d1 * inv;
}

// ============================ launcher =====================================
extern "C" void kernel_launch(void* const* d_in, const int* in_sizes, int n_in,
                              void* d_out, int out_size)
{
    const float* u_emb = (const float*)d_in[0];
    const float* f_emb = (const float*)d_in[1];
    const float* gpe   = (const float*)d_in[2];
    // d_in[3], d_in[4]: u_mask/f_mask — exactly causal; handled analytically.
    const float* Wq_w  = (const float*)d_in[5];
    const float* Wq_b  = (const float*)d_in[6];
    const float* Wkv_w = (const float*)d_in[7];
    const float* Wkv_b = (const float*)d_in[8];
    const float* Wp_w  = (const float*)d_in[9];
    const float* Wp_b  = (const float*)d_in[10];
    const float* Wu_w  = (const float*)d_in[11];
    const float* Wu_b  = (const float*)d_in[12];
    const float* Bfc   = (const float*)d_in[13];
    const float* Bfp   = (const float*)d_in[14];
    const float* Buc   = (const float*)d_in[15];
    const float* Bup   = (const float*)d_in[16];
    float* out = (float*)d_out;

    dim3 gp(16, 32, 4);
    proj_kernel<<<gp, 256>>>(f_emb, gpe, Wu_w, Wu_b, Wq_w, Wq_b, Wkv_w, Wkv_b,
                             Wp_w, Wp_b, Buc, Bup, Bfc, Bfp);

    const int ATTN_SMEM = 6 * 64 * QSTR * (int)sizeof(float);  // 104448 B
    cudaFuncSetAttribute(attn_kernel, cudaFuncAttributeMaxDynamicSharedMemorySize,
                         ATTN_SMEM);
    dim3 ga(16, 16, 2);
    attn_kernel<<<ga, 256, ATTN_SMEM>>>();

    dim3 gl(ROWS, 2);
    ln_kernel<<<gl, 256>>>(u_emb, f_emb, out);
}

// round 5
// speedup vs baseline: 2.2532x; 2.2532x over previous
#include <cuda_runtime.h>
#include <math.h>

namespace {
constexpr int SEQ   = 1024;
constexpr int EMBD  = 512;
constexpr int HDIM  = 64;
constexpr int BATCH = 2;
constexpr int ROWS  = BATCH * SEQ;   // 2048
constexpr int QS = 132;   // smem stride for 128-wide [Qc|Qp], [Kh|Kp] tiles
constexpr int VS = 68;    // smem stride for V tile
constexpr int PS = 72;    // smem stride for P tile
}

// ---------------- device scratch ----------------
__device__ __align__(16) float g_qc_u[ROWS * EMBD];
__device__ __align__(16) float g_qp_u[ROWS * EMBD];
__device__ __align__(16) float g_qc_f[ROWS * EMBD];
__device__ __align__(16) float g_qp_f[ROWS * EMBD];
__device__ __align__(16) float g_kh [ROWS * EMBD];
__device__ __align__(16) float g_vh [ROWS * EMBD];
__device__ __align__(16) float g_kph[ROWS * EMBD];
__device__ __align__(16) float g_attn_u[ROWS * EMBD];
__device__ __align__(16) float g_attn_f[ROWS * EMBD];

__device__ __forceinline__ float tanh_fast(float x) {
    x = fminf(fmaxf(x, -20.f), 20.f);
    float e = __expf(2.f * x);
    return __fdividef(e - 1.f, e + 1.f);
}

__device__ __forceinline__ float f2tf32(float x) {
    unsigned r;
    asm("cvt.rna.tf32.f32 %0, %1;" : "=r"(r) : "f"(x));
    return __uint_as_float(r);
}

__device__ __forceinline__ void cvt4(float4& v) {
    v.x = f2tf32(v.x); v.y = f2tf32(v.y); v.z = f2tf32(v.z); v.w = f2tf32(v.w);
}

// D += A(16x8,row) * B(8x8,col) with tf32 inputs, f32 accum.
__device__ __forceinline__ void mma8(float4& d, float a0, float a1, float a2, float a3,
                                     float b0, float b1) {
    asm volatile(
        "mma.sync.aligned.m16n8k8.row.col.f32.tf32.tf32.f32 "
        "{%0,%1,%2,%3},{%4,%5,%6,%7},{%8,%9},{%0,%1,%2,%3};"
        : "+f"(d.x), "+f"(d.y), "+f"(d.z), "+f"(d.w)
        : "r"(__float_as_uint(a0)), "r"(__float_as_uint(a1)),
          "r"(__float_as_uint(a2)), "r"(__float_as_uint(a3)),
          "r"(__float_as_uint(b0)), "r"(__float_as_uint(b1)));
}

// ================= projection GEMMs (tf32 mma + fused bias/tanh) ===========
// z=0: qu=f_emb@Wu -> qc_u=tanh(qu+Buc), qp_u=tanh(qu+Bup)
// z=1: qf=f_emb@Wq -> qc_f=tanh(qf+Bfc), qp_f=tanh(qf+Bfp)
// z=2: kv=f_emb@Wkv -> kh, vh (tanh)
// z=3: kp=gpe@Wp -> kph (tanh)
__global__ __launch_bounds__(128)
void proj_kernel(const float* __restrict__ f_emb, const float* __restrict__ gpe,
                 const float* __restrict__ Wu_w, const float* __restrict__ Wu_b,
                 const float* __restrict__ Wq_w, const float* __restrict__ Wq_b,
                 const float* __restrict__ Wkv_w, const float* __restrict__ Wkv_b,
                 const float* __restrict__ Wp_w, const float* __restrict__ Wp_b,
                 const float* __restrict__ Buc, const float* __restrict__ Bup,
                 const float* __restrict__ Bfc, const float* __restrict__ Bfp)
{
    const int z = blockIdx.z;
    const float* A; const float* W; const float* bias; int K, N;
    if (z == 0)      { A = f_emb; W = Wu_w;  bias = Wu_b;  K = 512; N = 512;  }
    else if (z == 1) { A = f_emb; W = Wq_w;  bias = Wq_b;  K = 512; N = 512;  }
    else if (z == 2) { A = f_emb; W = Wkv_w; bias = Wkv_b; K = 512; N = 1024; }
    else             { A = gpe;   W = Wp_w;  bias = Wp_b;  K = 128; N = 512;  }

    const int n0 = blockIdx.x * 64;
    if (n0 >= N) return;
    const int m0 = blockIdx.y * 64;

    __shared__ float As[64 * 36];   // [64 rows][32 k + pad4]
    __shared__ float Ws[32 * 68];   // [32 k][64 n + pad4]

    const int tid = threadIdx.x;
    const int lane = tid & 31, w = tid >> 5;
    const int g = lane >> 2, qd = lane & 3;

    float4 D[8];
#pragma unroll
    for (int j = 0; j < 8; j++) D[j] = make_float4(0.f, 0.f, 0.f, 0.f);

    for (int kb = 0; kb < K; kb += 32) {
        __syncthreads();
#pragma unroll
        for (int it = 0; it < 4; it++) {          // As: 512 float4
            int id = tid + 128 * it;
            int r = id >> 3, dq = (id & 7) * 4;
            float4 v = *(const float4*)&A[(m0 + r) * K + kb + dq];
            cvt4(v);
            *(float4*)&As[r * 36 + dq] = v;
        }
#pragma unroll
        for (int it = 0; it < 4; it++) {          // Ws: 512 float4
            int id = tid + 128 * it;
            int r = id >> 4, dq = (id & 15) * 4;
            float4 v = *(const float4*)&W[(kb + r) * N + n0 + dq];
            cvt4(v);
            *(float4*)&Ws[r * 68 + dq] = v;
        }
        __syncthreads();
#pragma unroll
        for (int kk = 0; kk < 4; kk++) {
            float a0 = As[(w*16 + g)     * 36 + kk*8 + qd];
            float a1 = As[(w*16 + g + 8) * 36 + kk*8 + qd];
            float a2 = As[(w*16 + g)     * 36 + kk*8 + qd + 4];
            float a3 = As[(w*16 + g + 8) * 36 + kk*8 + qd + 4];
#pragma unroll
            for (int j = 0; j < 8; j++) {
                float b0 = Ws[(kk*8 + qd)     * 68 + j*8 + g];
                float b1 = Ws[(kk*8 + qd + 4) * 68 + j*8 + g];
                mma8(D[j], a0, a1, a2, a3, b0, b1);
            }
        }
    }

    const int r0 = m0 + w*16 + g, r1 = r0 + 8;
#pragma unroll
    for (int j = 0; j < 8; j++) {
        int c = n0 + j*8 + 2*qd;
        float bx = bias[c], by = bias[c+1];
        float vx0 = D[j].x + bx, vy0 = D[j].y + by;   // row r0
        float vx1 = D[j].z + bx, vy1 = D[j].w + by;   // row r1
        if (z == 0 || z == 1) {
            const float* Bc = (z == 0) ? Buc : Bfc;
            const float* Bp = (z == 0) ? Bup : Bfp;
            float* qc = (z == 0) ? g_qc_u : g_qc_f;
            float* qp = (z == 0) ? g_qp_u : g_qp_f;
            float bcx = Bc[c], bcy = Bc[c+1], bpx = Bp[c], bpy = Bp[c+1];
            *(float2*)&qc[r0*EMBD + c] = make_float2(tanh_fast(vx0+bcx), tanh_fast(vy0+bcy));
            *(float2*)&qc[r1*EMBD + c] = make_float2(tanh_fast(vx1+bcx), tanh_fast(vy1+bcy));
            *(float2*)&qp[r0*EMBD + c] = make_float2(tanh_fast(vx0+bpx), tanh_fast(vy0+bpy));
            *(float2*)&qp[r1*EMBD + c] = make_float2(tanh_fast(vx1+bpx), tanh_fast(vy1+bpy));
        } else if (z == 2) {
            float* dst = (n0 < EMBD) ? g_kh : g_vh;
            int cc = (n0 < EMBD) ? c : c - EMBD;
            *(float2*)&dst[r0*EMBD + cc] = make_float2(tanh_fast(vx0), tanh_fast(vy0));
            *(float2*)&dst[r1*EMBD + cc] = make_float2(tanh_fast(vx1), tanh_fast(vy1));
        } else {
            *(float2*)&g_kph[r0*EMBD + c] = make_float2(tanh_fast(vx0), tanh_fast(vy0));
            *(float2*)&g_kph[r1*EMBD + c] = make_float2(tanh_fast(vx1), tanh_fast(vy1));
        }
    }
}

// ================= causal flash attention, tf32 mma ========================
// Score(j,k) = ([Qc_j|Qp_j'] . [Kh_k|Kp_k]) / 8  — single 64x64x128 GEMM.
// j' = j+1 for batch 0 (zero row at j=1023), j' = j for batch 1 (rel_shift).
__global__ __launch_bounds__(128, 2)
void attn_kernel()
{
    extern __shared__ float sm[];
    float* sQ  = sm;                 // [64][QS]  cols 0-63 Qc, 64-127 Qp
    float* sKK = sQ  + 64 * QS;      // [64][QS]  cols 0-63 Kh, 64-127 Kp
    float* sV  = sKK + 64 * QS;      // [64][VS]
    float* sP  = sV  + 64 * VS;      // [64][PS]  warp-private rows

    const int jt = 15 - (int)blockIdx.x;   // long blocks first
    const int b  = blockIdx.y >> 3;
    const int n  = blockIdx.y & 7;
    const int st = blockIdx.z;

    const float* __restrict__ qc = st ? g_qc_f : g_qc_u;
    const float* __restrict__ qp = st ? g_qp_f : g_qp_u;
    float* __restrict__ outp     = st ? g_attn_f : g_attn_u;

    const int tid = threadIdx.x;
    const int lane = tid & 31, w = tid >> 5;
    const int g = lane >> 2, qd = lane & 3;
    const int qoff = (b == 0) ? 1 : 0;

    // ---- load Q (tf32): 64 rows x 128 cols = 2048 float4 ----
#pragma unroll
    for (int it = 0; it < 16; it++) {
        int id = tid + 128 * it;
        int r = id >> 5, dq = (id & 31) * 4;
        int jg = jt*64 + r;
        float4 v;
        if (dq < 64) {
            v = *(const float4*)&qc[(b*SEQ + jg)*EMBD + n*HDIM + dq];
        } else if (b == 0 && jg == SEQ - 1) {
            v = make_float4(0.f, 0.f, 0.f, 0.f);
        } else {
            v = *(const float4*)&qp[(b*SEQ + jg + qoff)*EMBD + n*HDIM + dq - 64];
        }
        cvt4(v);
        *(float4*)&sQ[r * QS + dq] = v;
    }

    float m0 = -1e30f, m1 = -1e30f, l0 = 0.f, l1 = 0.f;
    float4 O[8];
#pragma unroll
    for (int j = 0; j < 8; j++) O[j] = make_float4(0.f, 0.f, 0.f, 0.f);

    const int r0loc = w*16 + g, r1loc = r0loc + 8;

    for (int kt = 0; kt <= jt; kt++) {
        __syncthreads();
        // ---- load K|Kp (2048 f4) + V (1024 f4), tf32 ----
#pragma unroll
        for (int it = 0; it < 24; it++) {
            int id = tid + 128 * it;
            if (id < 2048) {
                int r = id >> 5, dq = (id & 31) * 4;
                int grow = (b*SEQ + kt*64 + r)*EMBD + n*HDIM;
                float4 v = (dq < 64) ? *(const float4*)&g_kh[grow + dq]
                                     : *(const float4*)&g_kph[grow + dq - 64];
                cvt4(v);
                *(float4*)&sKK[r * QS + dq] = v;
            } else {
                int id2 = id - 2048;
                int r = id2 >> 4, dq = (id2 & 15) * 4;
                float4 v = *(const float4*)&g_vh[(b*SEQ + kt*64 + r)*EMBD + n*HDIM + dq];
                cvt4(v);
                *(float4*)&sV[r * VS + dq] = v;
            }
        }
        __syncthreads();

        // ---- scores: S[j] = 16x8 tile j, contraction over 128 ----
        float4 S[8];
#pragma unroll
        for (int j = 0; j < 8; j++) S[j] = make_float4(0.f, 0.f, 0.f, 0.f);
#pragma unroll 4
        for (int kk = 0; kk < 16; kk++) {
            float a0 = sQ[r0loc * QS + kk*8 + qd];
            float a1 = sQ[r1loc * QS + kk*8 + qd];
            float a2 = sQ[r0loc * QS + kk*8 + qd + 4];
            float a3 = sQ[r1loc * QS + kk*8 + qd + 4];
#pragma unroll
            for (int j = 0; j < 8; j++) {
                float b0 = sKK[(j*8 + g) * QS + kk*8 + qd];
                float b1 = sKK[(j*8 + g) * QS + kk*8 + qd + 4];
                mma8(S[j], a0, a1, a2, a3, b0, b1);
            }
        }

        // ---- online softmax (rows r0loc, r1loc; quad = lanes g*4+{0..3}) ----
        const bool diag = (kt == jt);
        float mt0 = -1e30f, mt1 = -1e30f;
#pragma unroll
        for (int j = 0; j < 8; j++) {
            float x = S[j].x * 0.125f, y = S[j].y * 0.125f;
            float zv = S[j].z * 0.125f, wv = S[j].w * 0.125f;
            if (diag) {
                int c0 = j*8 + 2*qd, c1 = c0 + 1;
                if (c0 > r0loc) x  = -1e30f;
                if (c1 > r0loc) y  = -1e30f;
                if (c0 > r1loc) zv = -1e30f;
                if (c1 > r1loc) wv = -1e30f;
            }
            S[j].x = x; S[j].y = y; S[j].z = zv; S[j].w = wv;
            mt0 = fmaxf(mt0, fmaxf(x, y));
            mt1 = fmaxf(mt1, fmaxf(zv, wv));
        }
        mt0 = fmaxf(mt0, __shfl_xor_sync(0xffffffffu, mt0, 1));
        mt0 = fmaxf(mt0, __shfl_xor_sync(0xffffffffu, mt0, 2));
        mt1 = fmaxf(mt1, __shfl_xor_sync(0xffffffffu, mt1, 1));
        mt1 = fmaxf(mt1, __shfl_xor_sync(0xffffffffu, mt1, 2));

        float mn0 = fmaxf(m0, mt0), mn1 = fmaxf(m1, mt1);
        float sc0 = __expf(m0 - mn0), sc1 = __expf(m1 - mn1);
        float ls0 = 0.f, ls1 = 0.f;
#pragma unroll
        for (int j = 0; j < 8; j++) {
            float px = __expf(S[j].x - mn0), py = __expf(S[j].y - mn0);
            float pz = __expf(S[j].z - mn1), pw = __expf(S[j].w - mn1);
            ls0 += px + py;  ls1 += pz + pw;
            *(float2*)&sP[r0loc * PS + j*8 + 2*qd] = make_float2(f2tf32(px), f2tf32(py));
            *(float2*)&sP[r1loc * PS + j*8 + 2*qd] = make_float2(f2tf32(pz), f2tf32(pw));
        }
        ls0 += __shfl_xor_sync(0xffffffffu, ls0, 1);
        ls0 += __shfl_xor_sync(0xffffffffu, ls0, 2);
        ls1 += __shfl_xor_sync(0xffffffffu, ls1, 1);
        ls1 += __shfl_xor_sync(0xffffffffu, ls1, 2);
        l0 = l0 * sc0 + ls0;  m0 = mn0;
        l1 = l1 * sc1 + ls1;  m1 = mn1;
#pragma unroll
        for (int j = 0; j < 8; j++) {
            O[j].x *= sc0; O[j].y *= sc0;
            O[j].z *= sc1; O[j].w *= sc1;
        }

        __syncwarp();   // sP is warp-private: order stores before fragment loads

        // ---- PV: O += P(16x64) @ V(64x64) ----
#pragma unroll 2
        for (int kk = 0; kk < 8; kk++) {
            float a0 = sP[r0loc * PS + kk*8 + qd];
            float a1 = sP[r1loc * PS + kk*8 + qd];
            float a2 = sP[r0loc * PS + kk*8 + qd + 4];
            float a3 = sP[r1loc * PS + kk*8 + qd + 4];
#pragma unroll
            for (int j = 0; j < 8; j++) {
                float b0 = sV[(kk*8 + qd)     * VS + j*8 + g];
                float b1 = sV[(kk*8 + qd + 4) * VS + j*8 + g];
                mma8(O[j], a0, a1, a2, a3, b0, b1);
            }
        }
        __syncwarp();   // PV reads done before next iter's softmax overwrites sP
    }

    const float inv0 = __fdividef(1.f, l0), inv1 = __fdividef(1.f, l1);
    const int row0 = (b*SEQ + jt*64 + r0loc) * EMBD + n*HDIM;
    const int row1 = row0 + 8 * EMBD;
#pragma unroll
    for (int j = 0; j < 8; j++) {
        int c = j*8 + 2*qd;
        *(float2*)&outp[row0 + c] = make_float2(O[j].x * inv0, O[j].y * inv0);
        *(float2*)&outp[row1 + c] = make_float2(O[j].z * inv1, O[j].w * inv1);
    }
}

// ================= residual + LayerNorm (eps 1e-5, no affine) ==============
__global__ __launch_bounds__(256)
void ln_kernel(const float* __restrict__ u_emb, const float* __restrict__ f_emb,
               float* __restrict__ out)
{
    const int row = blockIdx.x;
    const int st  = blockIdx.y;
    const float* emb  = st ? f_emb   : u_emb;
    const float* attn = st ? g_attn_f : g_attn_u;
    const int t = threadIdx.x;

    float x0 = emb[row*EMBD + t]       + attn[row*EMBD + t];
    float x1 = emb[row*EMBD + t + 256] + attn[row*EMBD + t + 256];

    __shared__ float red[16];
    float s = x0 + x1;
#pragma unroll
    for (int off = 16; off > 0; off >>= 1) s += __shfl_xor_sync(0xffffffffu, s, off);
    if ((t & 31) == 0) red[t >> 5] = s;
    __syncthreads();
    float tot = red[0]+red[1]+red[2]+red[3]+red[4]+red[5]+red[6]+red[7];
    float mean = tot * (1.f / 512.f);

    float d0 = x0 - mean, d1 = x1 - mean;
    float q = d0*d0 + d1*d1;
#pragma unroll
    for (int off = 16; off > 0; off >>= 1) q += __shfl_xor_sync(0xffffffffu, q, off);
    if ((t & 31) == 0) red[8 + (t >> 5)] = q;
    __syncthreads();
    float vtot = red[8]+red[9]+red[10]+red[11]+red[12]+red[13]+red[14]+red[15];
    float inv = rsqrtf(vtot * (1.f / 512.f) + 1e-5f);

    size_t base = (size_t)st * ROWS * EMBD + (size_t)row * EMBD;
    out[base + t]       = d0 * inv;
    out[base + t + 256] = d1 * inv;
}

// ============================ launcher =====================================
extern "C" void kernel_launch(void* const* d_in, const int* in_sizes, int n_in,
                              void* d_out, int out_size)
{
    (void)in_sizes; (void)n_in; (void)out_size;
    const float* u_emb = (const float*)d_in[0];
    const float* f_emb = (const float*)d_in[1];
    const float* gpe   = (const float*)d_in[2];
    // d_in[3], d_in[4]: u_mask/f_mask — exactly causal; handled analytically.
    const float* Wq_w  = (const float*)d_in[5];
    const float* Wq_b  = (const float*)d_in[6];
    const float* Wkv_w = (const float*)d_in[7];
    const float* Wkv_b = (const float*)d_in[8];
    const float* Wp_w  = (const float*)d_in[9];
    const float* Wp_b  = (const float*)d_in[10];
    const float* Wu_w  = (const float*)d_in[11];
    const float* Wu_b  = (const float*)d_in[12];
    const float* Bfc   = (const float*)d_in[13];
    const float* Bfp   = (const float*)d_in[14];
    const float* Buc   = (const float*)d_in[15];
    const float* Bup   = (const float*)d_in[16];
    float* out = (float*)d_out;

    dim3 gp(16, 32, 4);
    proj_kernel<<<gp, 128>>>(f_emb, gpe, Wu_w, Wu_b, Wq_w, Wq_b, Wkv_w, Wkv_b,
                             Wp_w, Wp_b, Buc, Bup, Bfc, Bfp);

    const int ATTN_SMEM = (64*QS*2 + 64*VS + 64*PS) * (int)sizeof(float); // 103424
    cudaFuncSetAttribute(attn_kernel, cudaFuncAttributeMaxDynamicSharedMemorySize,
                         ATTN_SMEM);
    dim3 ga(16, 16, 2);
    attn_kernel<<<ga, 128, ATTN_SMEM>>>();

    dim3 gl(ROWS, 2);
    ln_kernel<<<gl, 256>>>(u_emb, f_emb, out);
}

// round 6
// speedup vs baseline: 3.8108x; 1.6913x over previous
#include <cuda_runtime.h>
#include <cuda_bf16.h>
#include <math.h>

namespace {
constexpr int SEQ   = 1024;
constexpr int EMBD  = 512;
constexpr int HDIM  = 64;
constexpr int ROWS  = 2048;          // BATCH * SEQ
constexpr int SQ    = 136;           // smem stride (bf16) for 128-wide Q/K tiles
constexpr int SVP   = 72;            // smem stride (bf16) for 64-wide V/P tiles
}

// ---------------- device scratch (bf16 activations, f32 attention out) -----
__device__ __align__(16) __nv_bfloat16 g_qc_u[ROWS * EMBD];
__device__ __align__(16) __nv_bfloat16 g_qp_u[ROWS * EMBD];
__device__ __align__(16) __nv_bfloat16 g_qc_f[ROWS * EMBD];
__device__ __align__(16) __nv_bfloat16 g_qp_f[ROWS * EMBD];
__device__ __align__(16) __nv_bfloat16 g_kh [ROWS * EMBD];
__device__ __align__(16) __nv_bfloat16 g_vh [ROWS * EMBD];
__device__ __align__(16) __nv_bfloat16 g_kph[ROWS * EMBD];
__device__ __align__(16) float g_attn_u[ROWS * EMBD];
__device__ __align__(16) float g_attn_f[ROWS * EMBD];
// packed bf16 GEMM operands
__device__ __align__(16) __nv_bfloat16 g_Ab [ROWS * EMBD];       // f_emb
__device__ __align__(16) __nv_bfloat16 g_Wb [EMBD * 2048];       // [Wu|Wq|Wkv]
__device__ __align__(16) __nv_bfloat16 g_gb [ROWS * 128];        // gpe
__device__ __align__(16) __nv_bfloat16 g_Wpb[128 * EMBD];        // Wp
__device__ float g_bias[2048];                                   // [Wu_b|Wq_b|Wkv_b]

__device__ __forceinline__ float tanh_fast(float x) {
    x = fminf(fmaxf(x, -20.f), 20.f);
    float e = __expf(2.f * x);
    return __fdividef(e - 1.f, e + 1.f);
}

__device__ __forceinline__ unsigned smem_u32(const void* p) {
    return (unsigned)__cvta_generic_to_shared(p);
}

__device__ __forceinline__ void ldsm_x4(unsigned& r0, unsigned& r1, unsigned& r2,
                                        unsigned& r3, unsigned addr) {
    asm volatile("ldmatrix.sync.aligned.m8n8.x4.shared.b16 {%0,%1,%2,%3},[%4];"
                 : "=r"(r0), "=r"(r1), "=r"(r2), "=r"(r3) : "r"(addr));
}
__device__ __forceinline__ void ldsm_x4t(unsigned& r0, unsigned& r1, unsigned& r2,
                                         unsigned& r3, unsigned addr) {
    asm volatile("ldmatrix.sync.aligned.m8n8.x4.trans.shared.b16 {%0,%1,%2,%3},[%4];"
                 : "=r"(r0), "=r"(r1), "=r"(r2), "=r"(r3) : "r"(addr));
}

// D += A(16x16) * B(16x8), bf16 in, f32 accum
__device__ __forceinline__ void mma16(float4& d, unsigned a0, unsigned a1,
                                      unsigned a2, unsigned a3,
                                      unsigned b0, unsigned b1) {
    asm volatile(
        "mma.sync.aligned.m16n8k16.row.col.f32.bf16.bf16.f32 "
        "{%0,%1,%2,%3},{%4,%5,%6,%7},{%8,%9},{%0,%1,%2,%3};"
        : "+f"(d.x), "+f"(d.y), "+f"(d.z), "+f"(d.w)
        : "r"(a0), "r"(a1), "r"(a2), "r"(a3), "r"(b0), "r"(b1));
}

// ====================== prep: f32 -> bf16 packing ==========================
__global__ __launch_bounds__(256)
void prep_kernel(const float* __restrict__ f_emb, const float* __restrict__ gpe,
                 const float* __restrict__ Wu_w, const float* __restrict__ Wq_w,
                 const float* __restrict__ Wkv_w, const float* __restrict__ Wp_w,
                 const float* __restrict__ Wu_b, const float* __restrict__ Wq_b,
                 const float* __restrict__ Wkv_b)
{
    int i = blockIdx.x * blockDim.x + threadIdx.x;
    if (i < ROWS * EMBD) g_Ab[i] = __float2bfloat16(f_emb[i]);
    if (i < EMBD * 2048) {
        int k = i >> 11, c = i & 2047;
        float v = (c < 512)  ? Wu_w[k * 512 + c]
                : (c < 1024) ? Wq_w[k * 512 + c - 512]
                             : Wkv_w[k * 1024 + c - 1024];
        g_Wb[i] = __float2bfloat16(v);
    }
    if (i < ROWS * 128) g_gb[i] = __float2bfloat16(gpe[i]);
    if (i < 128 * EMBD) g_Wpb[i] = __float2bfloat16(Wp_w[i]);
    if (i < 2048) {
        g_bias[i] = (i < 512) ? Wu_b[i] : (i < 1024) ? Wq_b[i - 512] : Wkv_b[i - 1024];
    }
}

// ============ projection GEMMs: bf16 mma + ldmatrix + fused tanh ===========
// z=0: [qu|qf|kv] = f_emb @ [Wu|Wq|Wkv]  (M=2048, N=2048, K=512)
// z=1: kp = gpe @ Wp                      (M=2048, N=512,  K=128)
__global__ __launch_bounds__(128)
void proj_kernel(const float* __restrict__ Wp_b,
                 const float* __restrict__ Buc, const float* __restrict__ Bup,
                 const float* __restrict__ Bfc, const float* __restrict__ Bfp)
{
    const int z = blockIdx.z;
    const __nv_bfloat16* __restrict__ A  = z ? g_gb  : g_Ab;
    const __nv_bfloat16* __restrict__ Bm = z ? g_Wpb : g_Wb;
    const int K = z ? 128 : 512;
    const int N = z ? 512 : 2048;

    const int n0 = blockIdx.x * 64;
    if (n0 >= N) return;
    const int m0 = blockIdx.y * 64;

    __shared__ __nv_bfloat16 sA[64 * 40];   // stride 40 bf16 = 80B, LDSM clean
    __shared__ __nv_bfloat16 sB[32 * 72];   // stride 72 bf16 = 144B, LDSM clean

    const int tid = threadIdx.x;
    const int lane = tid & 31, w = tid >> 5;
    const int g = lane >> 2, qd = lane & 3;

    float4 D[8];
#pragma unroll
    for (int j = 0; j < 8; j++) D[j] = make_float4(0.f, 0.f, 0.f, 0.f);

    const unsigned aAddr = smem_u32(sA)
        + ((unsigned)((w * 16 + (lane & 15)) * 40 + ((lane >> 4) << 3))) * 2u;
    const unsigned bRow  = (lane & 7) + ((lane >> 3) & 1) * 8;   // k within step
    const unsigned bColP = (lane >> 4) << 3;                     // +8 n

    for (int kb = 0; kb < K; kb += 32) {
        __syncthreads();
#pragma unroll
        for (int it = 0; it < 2; it++) {          // sA: 256 f4
            int id = tid + 128 * it;
            int r = id >> 2, dq = (id & 3) * 8;
            *(float4*)&sA[r * 40 + dq] = *(const float4*)&A[(m0 + r) * K + kb + dq];
        }
#pragma unroll
        for (int it = 0; it < 2; it++) {          // sB: 256 f4
            int id = tid + 128 * it;
            int r = id >> 3, dq = (id & 7) * 8;
            *(float4*)&sB[r * 72 + dq] = *(const float4*)&Bm[(size_t)(kb + r) * N + n0 + dq];
        }
        __syncthreads();
#pragma unroll
        for (int ks = 0; ks < 2; ks++) {
            unsigned a0, a1, a2, a3;
            ldsm_x4(a0, a1, a2, a3, aAddr + (unsigned)ks * 32u);
#pragma unroll
            for (int jp = 0; jp < 4; jp++) {
                unsigned b0, b1, b2, b3;
                unsigned baddr = smem_u32(sB)
                    + ((unsigned)((ks * 16 + bRow) * 72 + jp * 16 + bColP)) * 2u;
                ldsm_x4t(b0, b1, b2, b3, baddr);
                mma16(D[2*jp],   a0, a1, a2, a3, b0, b1);
                mma16(D[2*jp+1], a0, a1, a2, a3, b2, b3);
            }
        }
    }

    const int r0 = m0 + w * 16 + g, r1 = r0 + 8;
#pragma unroll
    for (int j = 0; j < 8; j++) {
        const int ccol = n0 + j * 8 + 2 * qd;
        if (z == 1) {
            float bx = Wp_b[ccol], by = Wp_b[ccol + 1];
            *(__nv_bfloat162*)&g_kph[r0*EMBD + ccol] = __float22bfloat162_rn(
                make_float2(tanh_fast(D[j].x + bx), tanh_fast(D[j].y + by)));
            *(__nv_bfloat162*)&g_kph[r1*EMBD + ccol] = __float22bfloat162_rn(
                make_float2(tanh_fast(D[j].z + bx), tanh_fast(D[j].w + by)));
            continue;
        }
        const float bx = g_bias[ccol], by = g_bias[ccol + 1];
        const float vx0 = D[j].x + bx, vy0 = D[j].y + by;   // row r0
        const float vx1 = D[j].z + bx, vy1 = D[j].w + by;   // row r1
        if (ccol < 1024) {
            const bool isU = (ccol < 512);
            const int col = isU ? ccol : ccol - 512;
            const float* Bc = isU ? Buc : Bfc;
            const float* Bp = isU ? Bup : Bfp;
            __nv_bfloat16* qc = isU ? g_qc_u : g_qc_f;
            __nv_bfloat16* qp = isU ? g_qp_u : g_qp_f;
            float bcx = Bc[col], bcy = Bc[col+1], bpx = Bp[col], bpy = Bp[col+1];
            *(__nv_bfloat162*)&qc[r0*EMBD + col] = __float22bfloat162_rn(
                make_float2(tanh_fast(vx0+bcx), tanh_fast(vy0+bcy)));
            *(__nv_bfloat162*)&qc[r1*EMBD + col] = __float22bfloat162_rn(
                make_float2(tanh_fast(vx1+bcx), tanh_fast(vy1+bcy)));
            *(__nv_bfloat162*)&qp[r0*EMBD + col] = __float22bfloat162_rn(
                make_float2(tanh_fast(vx0+bpx), tanh_fast(vy0+bpy)));
            *(__nv_bfloat162*)&qp[r1*EMBD + col] = __float22bfloat162_rn(
                make_float2(tanh_fast(vx1+bpx), tanh_fast(vy1+bpy)));
        } else {
            const bool isK = (ccol < 1536);
            const int col = isK ? ccol - 1024 : ccol - 1536;
            __nv_bfloat16* dst = isK ? g_kh : g_vh;
            *(__nv_bfloat162*)&dst[r0*EMBD + col] = __float22bfloat162_rn(
                make_float2(tanh_fast(vx0), tanh_fast(vy0)));
            *(__nv_bfloat162*)&dst[r1*EMBD + col] = __float22bfloat162_rn(
                make_float2(tanh_fast(vx1), tanh_fast(vy1)));
        }
    }
}

// ============ causal flash attention: bf16 mma + ldmatrix ==================
// Score(j,k) = ([Qc_j|Qp_j'] . [Kh_k|Kp_k]) / 8 ; j'=j+1 for b=0 (zero row at
// j=1023), j'=j for b=1 — faithful _rel_shift semantics.
__global__ __launch_bounds__(128)
void attn_kernel()
{
    extern __shared__ __nv_bfloat16 smb[];
    __nv_bfloat16* sQ = smb;               // [64][SQ]  cols 0-63 Qc, 64-127 Qp
    __nv_bfloat16* sK = sQ + 64 * SQ;      // [64][SQ]  cols 0-63 Kh, 64-127 Kp
    __nv_bfloat16* sV = sK + 64 * SQ;      // [64][SVP]
    __nv_bfloat16* sP = sV + 64 * SVP;     // [64][SVP] warp-private rows

    const int jt = 15 - (int)blockIdx.x;   // long blocks first
    const int b  = blockIdx.y >> 3;
    const int n  = blockIdx.y & 7;
    const int st = blockIdx.z;

    const __nv_bfloat16* __restrict__ qc = st ? g_qc_f : g_qc_u;
    const __nv_bfloat16* __restrict__ qp = st ? g_qp_f : g_qp_u;
    float* __restrict__ outp             = st ? g_attn_f : g_attn_u;

    const int tid = threadIdx.x;
    const int lane = tid & 31, w = tid >> 5;
    const int g = lane >> 2, qd = lane & 3;
    const int qoff = (b == 0) ? 1 : 0;

    // ---- Q fill: 64 x 128 bf16 ----
#pragma unroll
    for (int it = 0; it < 8; it++) {
        int id = tid + 128 * it;
        int r = id >> 4, dq = (id & 15) * 8;
        int jg = jt * 64 + r;
        float4 v;
        if (dq < 64)
            v = *(const float4*)&qc[(b*SEQ + jg)*EMBD + n*HDIM + dq];
        else if (b == 0 && jg == SEQ - 1)
            v = make_float4(0.f, 0.f, 0.f, 0.f);
        else
            v = *(const float4*)&qp[(b*SEQ + jg + qoff)*EMBD + n*HDIM + dq - 64];
        *(float4*)&sQ[r * SQ + dq] = v;
    }

    float m0 = -1e30f, m1 = -1e30f, l0 = 0.f, l1 = 0.f;
    float4 O[8];
#pragma unroll
    for (int j = 0; j < 8; j++) O[j] = make_float4(0.f, 0.f, 0.f, 0.f);

    const int r0loc = w * 16 + g, r1loc = r0loc + 8;

    // ldmatrix address templates
    const unsigned qAddr = smem_u32(sQ)
        + ((unsigned)((w*16 + (lane & 15)) * SQ + ((lane >> 4) << 3))) * 2u;
    const unsigned pAddr = smem_u32(sP)
        + ((unsigned)((w*16 + (lane & 15)) * SVP + ((lane >> 4) << 3))) * 2u;
    const unsigned kRowP = (lane & 7) + ((lane >> 4) << 3);      // key within 16
    const unsigned kColP = ((lane >> 3) & 1) << 3;               // +8 d
    const unsigned vRowP = (lane & 7) + (((lane >> 3) & 1) << 3);// k within 16
    const unsigned vColP = (lane >> 4) << 3;                     // +8 n

    for (int kt = 0; kt <= jt; kt++) {
        __syncthreads();
#pragma unroll
        for (int it = 0; it < 8; it++) {          // K|Kp fill
            int id = tid + 128 * it;
            int r = id >> 4, dq = (id & 15) * 8;
            int grow = (b*SEQ + kt*64 + r)*EMBD + n*HDIM;
            float4 v = (dq < 64) ? *(const float4*)&g_kh[grow + dq]
                                 : *(const float4*)&g_kph[grow + dq - 64];
            *(float4*)&sK[r * SQ + dq] = v;
        }
#pragma unroll
        for (int it = 0; it < 4; it++) {          // V fill
            int id = tid + 128 * it;
            int r = id >> 3, dq = (id & 7) * 8;
            *(float4*)&sV[r * SVP + dq] =
                *(const float4*)&g_vh[(b*SEQ + kt*64 + r)*EMBD + n*HDIM + dq];
        }
        __syncthreads();

        // ---- scores: 64x64, contraction over 128 ----
        float4 S[8];
#pragma unroll
        for (int j = 0; j < 8; j++) S[j] = make_float4(0.f, 0.f, 0.f, 0.f);
#pragma unroll
        for (int ds = 0; ds < 8; ds++) {
            unsigned a0, a1, a2, a3;
            ldsm_x4(a0, a1, a2, a3, qAddr + (unsigned)ds * 32u);
#pragma unroll
            for (int jp = 0; jp < 4; jp++) {
                unsigned b0, b1, b2, b3;
                unsigned baddr = smem_u32(sK)
                    + ((unsigned)((jp*16 + kRowP) * SQ + ds*16 + kColP)) * 2u;
                ldsm_x4(b0, b1, b2, b3, baddr);
                mma16(S[2*jp],   a0, a1, a2, a3, b0, b1);
                mma16(S[2*jp+1], a0, a1, a2, a3, b2, b3);
            }
        }

        // ---- online softmax (rows r0loc, r1loc) ----
        const bool diag = (kt == jt);
        float mt0 = -1e30f, mt1 = -1e30f;
#pragma unroll
        for (int j = 0; j < 8; j++) {
            float x = S[j].x * 0.125f, y = S[j].y * 0.125f;
            float zv = S[j].z * 0.125f, wv = S[j].w * 0.125f;
            if (diag) {
                int c0 = j*8 + 2*qd, c1 = c0 + 1;
                if (c0 > r0loc) x  = -1e30f;
                if (c1 > r0loc) y  = -1e30f;
                if (c0 > r1loc) zv = -1e30f;
                if (c1 > r1loc) wv = -1e30f;
            }
            S[j].x = x; S[j].y = y; S[j].z = zv; S[j].w = wv;
            mt0 = fmaxf(mt0, fmaxf(x, y));
            mt1 = fmaxf(mt1, fmaxf(zv, wv));
        }
        mt0 = fmaxf(mt0, __shfl_xor_sync(0xffffffffu, mt0, 1));
        mt0 = fmaxf(mt0, __shfl_xor_sync(0xffffffffu, mt0, 2));
        mt1 = fmaxf(mt1, __shfl_xor_sync(0xffffffffu, mt1, 1));
        mt1 = fmaxf(mt1, __shfl_xor_sync(0xffffffffu, mt1, 2));

        float mn0 = fmaxf(m0, mt0), mn1 = fmaxf(m1, mt1);
        float sc0 = __expf(m0 - mn0), sc1 = __expf(m1 - mn1);
        float ls0 = 0.f, ls1 = 0.f;
#pragma unroll
        for (int j = 0; j < 8; j++) {
            float px = __expf(S[j].x - mn0), py = __expf(S[j].y - mn0);
            float pz = __expf(S[j].z - mn1), pw = __expf(S[j].w - mn1);
            ls0 += px + py;  ls1 += pz + pw;
            *(__nv_bfloat162*)&sP[r0loc * SVP + j*8 + 2*qd] =
                __float22bfloat162_rn(make_float2(px, py));
            *(__nv_bfloat162*)&sP[r1loc * SVP + j*8 + 2*qd] =
                __float22bfloat162_rn(make_float2(pz, pw));
        }
        ls0 += __shfl_xor_sync(0xffffffffu, ls0, 1);
        ls0 += __shfl_xor_sync(0xffffffffu, ls0, 2);
        ls1 += __shfl_xor_sync(0xffffffffu, ls1, 1);
        ls1 += __shfl_xor_sync(0xffffffffu, ls1, 2);
        l0 = l0 * sc0 + ls0;  m0 = mn0;
        l1 = l1 * sc1 + ls1;  m1 = mn1;
#pragma unroll
        for (int j = 0; j < 8; j++) {
            O[j].x *= sc0; O[j].y *= sc0;
            O[j].z *= sc1; O[j].w *= sc1;
        }

        __syncwarp();   // sP warp-private: stores before ldmatrix reads

        // ---- PV: O += P(16x64) @ V(64x64) ----
#pragma unroll
        for (int ks = 0; ks < 4; ks++) {
            unsigned a0, a1, a2, a3;
            ldsm_x4(a0, a1, a2, a3, pAddr + (unsigned)ks * 32u);
#pragma unroll
            for (int jp = 0; jp < 4; jp++) {
                unsigned b0, b1, b2, b3;
                unsigned vaddr = smem_u32(sV)
                    + ((unsigned)((ks*16 + vRowP) * SVP + jp*16 + vColP)) * 2u;
                ldsm_x4t(b0, b1, b2, b3, vaddr);
                mma16(O[2*jp],   a0, a1, a2, a3, b0, b1);
                mma16(O[2*jp+1], a0, a1, a2, a3, b2, b3);
            }
        }
        __syncwarp();   // PV reads done before next iter overwrites sP
    }

    const float inv0 = __fdividef(1.f, l0), inv1 = __fdividef(1.f, l1);
    const int row0 = (b*SEQ + jt*64 + r0loc) * EMBD + n*HDIM;
    const int row1 = row0 + 8 * EMBD;
#pragma unroll
    for (int j = 0; j < 8; j++) {
        int c = j*8 + 2*qd;
        *(float2*)&outp[row0 + c] = make_float2(O[j].x * inv0, O[j].y * inv0);
        *(float2*)&outp[row1 + c] = make_float2(O[j].z * inv1, O[j].w * inv1);
    }
}

// ================= residual + LayerNorm (eps 1e-5, no affine) ==============
__global__ __launch_bounds__(256)
void ln_kernel(const float* __restrict__ u_emb, const float* __restrict__ f_emb,
               float* __restrict__ out)
{
    const int row = blockIdx.x;
    const int st  = blockIdx.y;
    const float* emb  = st ? f_emb   : u_emb;
    const float* attn = st ? g_attn_f : g_attn_u;
    const int t = threadIdx.x;

    float x0 = emb[row*EMBD + t]       + attn[row*EMBD + t];
    float x1 = emb[row*EMBD + t + 256] + attn[row*EMBD + t + 256];

    __shared__ float red[16];
    float s = x0 + x1;
#pragma unroll
    for (int off = 16; off > 0; off >>= 1) s += __shfl_xor_sync(0xffffffffu, s, off);
    if ((t & 31) == 0) red[t >> 5] = s;
    __syncthreads();
    float tot = red[0]+red[1]+red[2]+red[3]+red[4]+red[5]+red[6]+red[7];
    float mean = tot * (1.f / 512.f);

    float d0 = x0 - mean, d1 = x1 - mean;
    float q = d0*d0 + d1*d1;
#pragma unroll
    for (int off = 16; off > 0; off >>= 1) q += __shfl_xor_sync(0xffffffffu, q, off);
    if ((t & 31) == 0) red[8 + (t >> 5)] = q;
    __syncthreads();
    float vtot = red[8]+red[9]+red[10]+red[11]+red[12]+red[13]+red[14]+red[15];
    float inv = rsqrtf(vtot * (1.f / 512.f) + 1e-5f);

    size_t base = (size_t)st * ROWS * EMBD + (size_t)row * EMBD;
    out[base + t]       = d0 * inv;
    out[base + t + 256] = d1 * inv;
}

// ============================ launcher =====================================
extern "C" void kernel_launch(void* const* d_in, const int* in_sizes, int n_in,
                              void* d_out, int out_size)
{
    (void)in_sizes; (void)n_in; (void)out_size;
    const float* u_emb = (const float*)d_in[0];
    const float* f_emb = (const float*)d_in[1];
    const float* gpe   = (const float*)d_in[2];
    // d_in[3], d_in[4]: u_mask/f_mask — exactly causal; handled analytically.
    const float* Wq_w  = (const float*)d_in[5];
    const float* Wq_b  = (const float*)d_in[6];
    const float* Wkv_w = (const float*)d_in[7];
    const float* Wkv_b = (const float*)d_in[8];
    const float* Wp_w  = (const float*)d_in[9];
    const float* Wp_b  = (const float*)d_in[10];
    const float* Wu_w  = (const float*)d_in[11];
    const float* Wu_b  = (const float*)d_in[12];
    const float* Bfc   = (const float*)d_in[13];
    const float* Bfp   = (const float*)d_in[14];
    const float* Buc   = (const float*)d_in[15];
    const float* Bup   = (const float*)d_in[16];
    float* out = (float*)d_out;

    prep_kernel<<<4096, 256>>>(f_emb, gpe, Wu_w, Wq_w, Wkv_w, Wp_w,
                               Wu_b, Wq_b, Wkv_b);

    dim3 gp(32, 32, 2);
    proj_kernel<<<gp, 128>>>(Wp_b, Buc, Bup, Bfc, Bfp);

    const int ATTN_SMEM = (64*SQ*2 + 64*SVP*2) * (int)sizeof(__nv_bfloat16); // 53248
    cudaFuncSetAttribute(attn_kernel, cudaFuncAttributeMaxDynamicSharedMemorySize,
                         ATTN_SMEM);
    dim3 ga(16, 16, 2);
    attn_kernel<<<ga, 128, ATTN_SMEM>>>();

    dim3 gl(ROWS, 2);
    ln_kernel<<<gl, 256>>>(u_emb, f_emb, out);
}